// round 16
// baseline (speedup 1.0000x reference)
#include <cuda_runtime.h>
#include <cuda_fp16.h>
#include <cstdint>

#define Nn 200000
#define Ee 3200000
#define C  16
#define EPSV 1e-5f
#define SB  512
#define SBLK ((Nn + SB - 1) / SB)   // 391
#define L1B  6250                   // lin1 blocks (8 warps x 4 rows)
#define FILB 12500                  // fill blocks (256 threads each)

// ---------------- scratch (no allocations allowed) ----------------
__device__ __align__(16) float  g_dinv[Nn];    // rsqrt(deg+1)
__device__ __align__(16) __half g_h[Nn * C];   // node features after linear (fp16)
__device__ __align__(16) float  g_agg[Nn * C]; // aggregation result (bias included, fp32)
__device__ __align__(16) float  g_stats[64];   // layer1: [0:16) sum [16:32) sq; layer2: +32
__device__ int  g_deg[Nn];                     // in-degree (edges only)
__device__ int  g_off[Nn];                     // CSR exclusive offsets (EVEN, padded)
__device__ int  g_cur[Nn];                     // fill cursors
__device__ int  g_tmpI[Nn];                    // scan temp (inclusive, padded degrees)
__device__ int  g_bsum[SB];                    // block sums for scan
__device__ __align__(16) int2 g_csr[Ee + Nn];  // {src, nrm}; padded to even per node

// ---------------- f32x2 packed math helpers ----------------
__device__ __forceinline__ unsigned long long pack2(float a, float b) {
    unsigned long long r;
    asm("mov.b64 %0, {%1, %2};" : "=l"(r) : "r"(__float_as_uint(a)), "r"(__float_as_uint(b)));
    return r;
}
__device__ __forceinline__ void unpack2(float& a, float& b, unsigned long long v) {
    unsigned lo, hi;
    asm("mov.b64 {%0, %1}, %2;" : "=r"(lo), "=r"(hi) : "l"(v));
    a = __uint_as_float(lo);
    b = __uint_as_float(hi);
}
__device__ __forceinline__ unsigned long long fma2(unsigned long long a, unsigned long long b,
                                                   unsigned long long c) {
    unsigned long long d;
    asm("fma.rn.f32x2 %0, %1, %2, %3;" : "=l"(d) : "l"(a), "l"(b), "l"(c));
    return d;
}

// ---------------- init: zero degrees + zero both stats buffers ----------------
__global__ void k_init() {
    int i = blockIdx.x * blockDim.x + threadIdx.x;
    if (i < Nn) g_deg[i] = 0;
    if (blockIdx.x == 0 && threadIdx.x < 64) g_stats[threadIdx.x] = 0.0f;
}

// edge_index is INT32 on device (harness converts int64 -> int32)
__global__ void k_deg_count(const int* __restrict__ ei) {
    int e = blockIdx.x * blockDim.x + threadIdx.x;
    if (e < Ee) {
        unsigned d = (unsigned)ei[Ee + e];
        if (d < Nn) atomicAdd(&g_deg[d], 1);
    }
}

// scan stage 1 (+dinv fused): inclusive scan over EVEN-PADDED degrees
__global__ void k_scan1() {
    __shared__ int sm[SB];
    int t = threadIdx.x;
    int idx = blockIdx.x * SB + t;
    int v = (idx < Nn) ? g_deg[idx] : 0;
    if (idx < Nn) g_dinv[idx] = rsqrtf((float)(v + 1));  // +1 self-loop
    int vp = (v + 1) & ~1;                               // pad to even
    sm[t] = vp;
    __syncthreads();
    for (int o = 1; o < SB; o <<= 1) {
        int a = (t >= o) ? sm[t - o] : 0;
        __syncthreads();
        sm[t] += a;
        __syncthreads();
    }
    if (idx < Nn) g_tmpI[idx] = sm[t];
    if (t == SB - 1) g_bsum[blockIdx.x] = sm[t];
}

// scan stage 2+3 merged: offsets (even) + cursors + zero the pad slot of odd nodes
__global__ void k_scan3() {
    __shared__ int red[SB];
    int t = threadIdx.x;
    red[t] = (t < blockIdx.x && t < SBLK) ? g_bsum[t] : 0;
    __syncthreads();
    for (int o = SB / 2; o > 0; o >>= 1) {
        if (t < o) red[t] += red[t + o];
        __syncthreads();
    }
    int S = red[0];
    int idx = blockIdx.x * SB + t;
    if (idx < Nn) {
        int deg = g_deg[idx];
        int pad = (deg + 1) & ~1;
        int excl = g_tmpI[idx] - pad + S;
        g_off[idx] = excl;
        g_cur[idx] = excl;
        if (deg & 1) g_csr[excl + deg] = make_int2(0, 0);  // pad record: weight 0
    }
}

// ---------------- FUSED lin1 + fill ----------------
// Independent work merged for same-stream concurrency: fill (LSU/atomic-bound,
// ~15us) hides under lin1 (FMA/DRAM-bound, ~66us). Interleave via bid%3:
// m==0 -> lin1 block r (r in [0,L1B)), else fill block 2r+(m-1) (in [0,FILB)).
__global__ void k_lin1_fill(const float* __restrict__ x, const float* __restrict__ W1,
                            const int* __restrict__ ei) {
    int bid = blockIdx.x;
    int r = bid / 3;
    int m = bid - r * 3;

    if (m != 0) {
        // ---- fill body: writes EVERY claimed slot (invalid src -> {0,0}) ----
        int fid = 2 * r + (m - 1);
        int e = fid * 256 + threadIdx.x;
        if (e < Ee) {
            unsigned s = (unsigned)ei[e];
            unsigned d = (unsigned)ei[Ee + e];
            if (d < Nn) {
                int   ssrc = 0;
                float nrm  = 0.0f;
                if (s < Nn) { ssrc = (int)s; nrm = g_dinv[s] * g_dinv[d]; }
                int slot = atomicAdd(&g_cur[d], 1);
                g_csr[slot] = make_int2(ssrc, __float_as_int(nrm));
            }
        }
        return;
    }

    // ---- lin1 body (R10 proven core, fp16 epilogue), block index r ----
    __shared__ __align__(16) float Ws[256 * 16];
    int tid = threadIdx.x;
#pragma unroll 4
    for (int i = tid; i < 256 * 16; i += 256) {
        int k = i >> 4, o = i & 15;
        int slot = (o >> 2) ^ ((k >> 1) & 3);
        Ws[(k << 4) + (slot << 2) + (o & 3)] = W1[i];
    }
    __syncthreads();

    int warp = tid >> 5, lane = tid & 31;
    int r0 = (r * 8 + warp) * 4;

    unsigned long long acc2[32];
#pragma unroll
    for (int j = 0; j < 32; j++) acc2[j] = 0ULL;

#pragma unroll
    for (int s = 0; s < 8; s++) {
        int k = (s << 5) | lane;
        float x0 = x[(size_t)(r0 + 0) * 256 + k];
        float x1 = x[(size_t)(r0 + 1) * 256 + k];
        float x2 = x[(size_t)(r0 + 2) * 256 + k];
        float x3 = x[(size_t)(r0 + 3) * 256 + k];
        unsigned long long xp0 = pack2(x0, x0);
        unsigned long long xp1 = pack2(x1, x1);
        unsigned long long xp2 = pack2(x2, x2);
        unsigned long long xp3 = pack2(x3, x3);

        const ulonglong2* wrow = (const ulonglong2*)(Ws + (k << 4));
        int sw = (k >> 1) & 3;
        ulonglong2 wq0 = wrow[0 ^ sw];
        ulonglong2 wq1 = wrow[1 ^ sw];
        ulonglong2 wq2 = wrow[2 ^ sw];
        ulonglong2 wq3 = wrow[3 ^ sw];
        unsigned long long w2[8] = {wq0.x, wq0.y, wq1.x, wq1.y, wq2.x, wq2.y, wq3.x, wq3.y};

#pragma unroll
        for (int o2 = 0; o2 < 8; o2++) {
            acc2[0 * 8 + o2] = fma2(xp0, w2[o2], acc2[0 * 8 + o2]);
            acc2[1 * 8 + o2] = fma2(xp1, w2[o2], acc2[1 * 8 + o2]);
            acc2[2 * 8 + o2] = fma2(xp2, w2[o2], acc2[2 * 8 + o2]);
            acc2[3 * 8 + o2] = fma2(xp3, w2[o2], acc2[3 * 8 + o2]);
        }
    }

    float vals[64];
#pragma unroll
    for (int j = 0; j < 32; j++) unpack2(vals[2 * j], vals[2 * j + 1], acc2[j]);

    const unsigned FULL = 0xffffffffu;
#define FOLD_STAGE(n, mm)                                                       \
    {                                                                           \
        bool hi = (lane & (mm)) != 0;                                           \
        _Pragma("unroll")                                                       \
        for (int t = 0; t < (n) / 2; t++) {                                     \
            float mine = hi ? vals[t + (n) / 2] : vals[t];                      \
            float send = hi ? vals[t] : vals[t + (n) / 2];                      \
            vals[t] = mine + __shfl_xor_sync(FULL, send, (mm));                 \
        }                                                                       \
    }
    FOLD_STAGE(64, 16)
    FOLD_STAGE(32, 8)
    FOLD_STAGE(16, 4)
    FOLD_STAGE(8, 2)
    FOLD_STAGE(4, 1)
#undef FOLD_STAGE

    int i = (((lane >> 4) & 1) << 1) | ((lane >> 3) & 1);
    int o = (((lane >> 2) & 1) << 3) | (((lane >> 1) & 1) << 2) | ((lane & 1) << 1);
    int row = r0 + i;
    __half2 hp = __floats2half2_rn(vals[0], vals[1]);     // cols o, o+1
    ((unsigned*)g_h)[row * 8 + (o >> 1)] = *(unsigned*)&hp;
}

// ---------------- gather core (quad-per-node, padded CSR, branch-free) ----------
__device__ __forceinline__ float4 gather_node(int node, int t) {
    int beg  = g_off[node];                 // always even
    int cnt  = g_deg[node];
    int nit  = (cnt + 1) >> 1;              // int4 iterations over padded records
    float di = g_dinv[node];
    float ss = di * di;

    const uint2* h2 = (const uint2*)g_h;    // 8B granule: index = node*4 + t
    uint2 araw = h2[(node << 2) + t];
    float2 a01 = __half22float2(*(__half2*)&araw.x);
    float2 a23 = __half22float2(*(__half2*)&araw.y);
    float4 acc;
    acc.x = ss * a01.x; acc.y = ss * a01.y; acc.z = ss * a23.x; acc.w = ss * a23.y;

    const int4* cp = (const int4*)(g_csr + beg);
#pragma unroll 4
    for (int it = 0; it < nit; it++) {
        int4 rr = cp[it];                   // 2 records: {s0, n0, s1, n1}
        float w0 = __int_as_float(rr.y);
        float w1 = __int_as_float(rr.w);
        uint2 vr0 = h2[((unsigned)rr.x << 2) + t];
        uint2 vr1 = h2[((unsigned)rr.z << 2) + t];
        float2 p01 = __half22float2(*(__half2*)&vr0.x);
        float2 p23 = __half22float2(*(__half2*)&vr0.y);
        float2 q01 = __half22float2(*(__half2*)&vr1.x);
        float2 q23 = __half22float2(*(__half2*)&vr1.y);
        acc.x = fmaf(w0, p01.x, acc.x);
        acc.y = fmaf(w0, p01.y, acc.y);
        acc.z = fmaf(w0, p23.x, acc.z);
        acc.w = fmaf(w0, p23.y, acc.w);
        acc.x = fmaf(w1, q01.x, acc.x);
        acc.y = fmaf(w1, q01.y, acc.y);
        acc.z = fmaf(w1, q23.x, acc.z);
        acc.w = fmaf(w1, q23.y, acc.w);
    }
    return acc;
}

// gather + bias + fused BN stats (sum/sumsq per column into g_stats[so..])
__global__ void k_gather_agg(const float* __restrict__ bias, int so) {
    __shared__ float bsum[16], bsq[16];
    if (threadIdx.x < 16) { bsum[threadIdx.x] = 0.0f; bsq[threadIdx.x] = 0.0f; }
    __syncthreads();

    int gid  = blockIdx.x * blockDim.x + threadIdx.x;
    int node = gid >> 2;
    int t    = gid & 3;
    int lane = threadIdx.x & 31;

    float4 acc = gather_node(node, t);
    float4 b4  = ((const float4*)bias)[t];
    acc.x += b4.x; acc.y += b4.y; acc.z += b4.z; acc.w += b4.w;
    ((float4*)g_agg)[(node << 2) + t] = acc;

    float4 s1 = acc;
    float4 s2;
    s2.x = acc.x * acc.x; s2.y = acc.y * acc.y; s2.z = acc.z * acc.z; s2.w = acc.w * acc.w;
    const unsigned FULL = 0xffffffffu;
#pragma unroll
    for (int m = 4; m <= 16; m <<= 1) {
        s1.x += __shfl_xor_sync(FULL, s1.x, m);
        s1.y += __shfl_xor_sync(FULL, s1.y, m);
        s1.z += __shfl_xor_sync(FULL, s1.z, m);
        s1.w += __shfl_xor_sync(FULL, s1.w, m);
        s2.x += __shfl_xor_sync(FULL, s2.x, m);
        s2.y += __shfl_xor_sync(FULL, s2.y, m);
        s2.z += __shfl_xor_sync(FULL, s2.z, m);
        s2.w += __shfl_xor_sync(FULL, s2.w, m);
    }
    if (lane < 4) {
        atomicAdd(&bsum[t * 4 + 0], s1.x);
        atomicAdd(&bsum[t * 4 + 1], s1.y);
        atomicAdd(&bsum[t * 4 + 2], s1.z);
        atomicAdd(&bsum[t * 4 + 3], s1.w);
        atomicAdd(&bsq[t * 4 + 0], s2.x);
        atomicAdd(&bsq[t * 4 + 1], s2.y);
        atomicAdd(&bsq[t * 4 + 2], s2.z);
        atomicAdd(&bsq[t * 4 + 3], s2.w);
    }
    __syncthreads();
    if (threadIdx.x < 16) {
        atomicAdd(&g_stats[so + threadIdx.x], bsum[threadIdx.x]);
        atomicAdd(&g_stats[so + 16 + threadIdx.x], bsq[threadIdx.x]);
    }
}

__global__ void k_gather_out(float* __restrict__ out, const float* __restrict__ bias) {
    int gid  = blockIdx.x * blockDim.x + threadIdx.x;
    int node = gid >> 2;
    if (node >= Nn) return;
    int t = gid & 3;
    float4 acc = gather_node(node, t);
    float4 b4  = ((const float4*)bias)[t];
    acc.x += b4.x; acc.y += b4.y; acc.z += b4.z; acc.w += b4.w;
    ((float4*)out)[(node << 2) + t] = acc;
}

// ---------------- fused BNfinal+BN+ReLU+16x16 linear (fp16 h output) ----------------
__global__ void k_lin_mid(const float* __restrict__ W,
                          const float* __restrict__ gamma,
                          const float* __restrict__ beta, int so) {
    __shared__ float Ws[256];
    __shared__ float sc_s[16], sh_s[16];
    if (threadIdx.x < 256) Ws[threadIdx.x] = W[threadIdx.x];
    if (threadIdx.x < 16) {
        float sum = g_stats[so + threadIdx.x];
        float sq  = g_stats[so + 16 + threadIdx.x];
        float mu  = sum / (float)Nn;
        float var = sq / (float)Nn - mu * mu;
        float sc  = gamma[threadIdx.x] * rsqrtf(var + EPSV);
        sc_s[threadIdx.x] = sc;
        sh_s[threadIdx.x] = beta[threadIdx.x] - mu * sc;
    }
    __syncthreads();

    int row = blockIdx.x * blockDim.x + threadIdx.x;
    if (row >= Nn) return;

    float z[16];
    const float4* ap = (const float4*)(g_agg + (size_t)row * 16);
#pragma unroll
    for (int j = 0; j < 4; j++) {
        float4 v = ap[j];
        const float* vv = (const float*)&v;
#pragma unroll
        for (int i = 0; i < 4; i++) {
            int k = j * 4 + i;
            z[k] = fmaxf(fmaf(sc_s[k], vv[i], sh_s[k]), 0.0f);
        }
    }

    float o[16];
#pragma unroll
    for (int c = 0; c < 16; c++) o[c] = 0.0f;
#pragma unroll
    for (int k = 0; k < 16; k++) {
        float zk = z[k];
        const float* wr = &Ws[k * 16];
#pragma unroll
        for (int c = 0; c < 16; c++) o[c] = fmaf(zk, wr[c], o[c]);
    }

    // emit fp16: 16 cols -> 8 half2 -> 2x uint4
    uint4* hv = (uint4*)((__half*)g_h + (size_t)row * 16);
#pragma unroll
    for (int j = 0; j < 2; j++) {
        __half2 h0 = __floats2half2_rn(o[j*8+0], o[j*8+1]);
        __half2 h1 = __floats2half2_rn(o[j*8+2], o[j*8+3]);
        __half2 h2 = __floats2half2_rn(o[j*8+4], o[j*8+5]);
        __half2 h3 = __floats2half2_rn(o[j*8+6], o[j*8+7]);
        uint4 st;
        st.x = *(unsigned*)&h0;
        st.y = *(unsigned*)&h1;
        st.z = *(unsigned*)&h2;
        st.w = *(unsigned*)&h3;
        hv[j] = st;
    }
}

// ---------------- launch ----------------
extern "C" void kernel_launch(void* const* d_in, const int* in_sizes, int n_in,
                              void* d_out, int out_size) {
    // Identify inputs by SIZE (robust to metadata ordering)
    const float* x  = nullptr;
    const int*   ei = nullptr;
    const float* W1 = nullptr;
    const float* W2 = nullptr;
    const float* W3 = nullptr;
    const float* v16[8] = {nullptr};
    int n16 = 0;
    for (int i = 0; i < n_in; i++) {
        int sz = in_sizes[i];
        if      (sz == 51200000) x  = (const float*)d_in[i];
        else if (sz == 6400000)  ei = (const int*)d_in[i];
        else if (sz == 4096)     W1 = (const float*)d_in[i];
        else if (sz == 256)      { if (!W2) W2 = (const float*)d_in[i]; else W3 = (const float*)d_in[i]; }
        else if (sz == 16 && n16 < 8) v16[n16++] = (const float*)d_in[i];
    }
    const float* b1  = v16[0];
    const float* g1  = v16[1];
    const float* be1 = v16[2];
    const float* b2  = v16[3];
    const float* g2  = v16[4];
    const float* be2 = v16[5];
    const float* b3  = v16[6];
    float* out = (float*)d_out;

    const int TB    = 256;
    const int nblk  = (Nn + TB - 1) / TB;
    const int eblk  = (Ee + TB - 1) / TB;   // 12500 == FILB
    const int gblk  = (Nn * 4) / TB;        // 3125 exact

    // ----- CSR build + fused(lin1,fill) -----
    k_init<<<nblk, TB>>>();                 // 0
    k_deg_count<<<eblk, TB>>>(ei);          // 1
    k_scan1<<<SBLK, SB>>>();                // 2
    k_scan3<<<SBLK, SB>>>();                // 3  <-- profiled slot
    k_lin1_fill<<<L1B + FILB, TB>>>(x, W1, ei);  // 4: fill hides under lin1

    // ----- layer 1 -----
    k_gather_agg<<<gblk, TB>>>(b1, 0);      // 5
    // ----- layer 2 -----
    k_lin_mid<<<nblk, TB>>>(W2, g1, be1, 0);    // 6
    k_gather_agg<<<gblk, TB>>>(b2, 32);         // 7
    // ----- layer 3 -----
    k_lin_mid<<<nblk, TB>>>(W3, g2, be2, 32);   // 8
    k_gather_out<<<gblk, TB>>>(out, b3);        // 9
}

// round 17
// speedup vs baseline: 1.1325x; 1.1325x over previous
#include <cuda_runtime.h>
#include <cuda_fp16.h>
#include <cstdint>

#define Nn 200000
#define Ee 3200000
#define C  16
#define EPSV 1e-5f
#define SB  512
#define SBLK ((Nn + SB - 1) / SB)   // 391

// ---------------- scratch (no allocations allowed) ----------------
__device__ __align__(16) float  g_dinv[Nn];    // rsqrt(deg+1)
__device__ __align__(16) __half g_h[Nn * C];   // node features after linear (fp16)
__device__ __align__(16) float  g_agg[Nn * C]; // aggregation result (bias included, fp32)
__device__ __align__(16) float  g_stats[64];   // layer1: [0:16) sum [16:32) sq; layer2: +32
__device__ int  g_deg[Nn];                     // in-degree (edges only)
__device__ int  g_off[Nn];                     // CSR offsets (EVEN, padded; unordered partition)
__device__ int  g_cur[Nn];                     // fill cursors
__device__ int  g_base;                        // global cursor for single-pass scan
__device__ __align__(16) int2 g_csr[Ee + Nn];  // {src, nrm}; padded to even per node

// ---------------- f32x2 packed math helpers ----------------
__device__ __forceinline__ unsigned long long pack2(float a, float b) {
    unsigned long long r;
    asm("mov.b64 %0, {%1, %2};" : "=l"(r) : "r"(__float_as_uint(a)), "r"(__float_as_uint(b)));
    return r;
}
__device__ __forceinline__ void unpack2(float& a, float& b, unsigned long long v) {
    unsigned lo, hi;
    asm("mov.b64 {%0, %1}, %2;" : "=r"(lo), "=r"(hi) : "l"(v));
    a = __uint_as_float(lo);
    b = __uint_as_float(hi);
}
__device__ __forceinline__ unsigned long long fma2(unsigned long long a, unsigned long long b,
                                                   unsigned long long c) {
    unsigned long long d;
    asm("fma.rn.f32x2 %0, %1, %2, %3;" : "=l"(d) : "l"(a), "l"(b), "l"(c));
    return d;
}

// ---------------- init: zero degrees + stats + global cursor ----------------
__global__ void k_init() {
    int i = blockIdx.x * blockDim.x + threadIdx.x;
    if (i < Nn) g_deg[i] = 0;
    if (blockIdx.x == 0 && threadIdx.x < 64) g_stats[threadIdx.x] = 0.0f;
    if (blockIdx.x == 0 && threadIdx.x == 0) g_base = 0;
}

// edge_index is INT32 on device (harness converts int64 -> int32)
__global__ void k_deg_count(const int* __restrict__ ei) {
    int e = blockIdx.x * blockDim.x + threadIdx.x;
    if (e < Ee) {
        unsigned d = (unsigned)ei[Ee + e];
        if (d < Nn) atomicAdd(&g_deg[d], 1);
    }
}

// single-pass scan: block-local inclusive scan of even-padded degrees, block base
// claimed via atomicAdd (UNORDERED partition -- valid since offsets only need to
// be disjoint). Also: dinv, cursors, and zeroing the pad slot of odd-degree nodes.
__global__ void k_scanA() {
    __shared__ int sm[SB];
    __shared__ int sbase;
    int t = threadIdx.x;
    int idx = blockIdx.x * SB + t;
    int v = (idx < Nn) ? g_deg[idx] : 0;
    if (idx < Nn) g_dinv[idx] = rsqrtf((float)(v + 1));  // +1 self-loop
    int vp = (v + 1) & ~1;                               // pad to even
    sm[t] = vp;
    __syncthreads();
    for (int o = 1; o < SB; o <<= 1) {
        int a = (t >= o) ? sm[t - o] : 0;
        __syncthreads();
        sm[t] += a;
        __syncthreads();
    }
    if (t == SB - 1) sbase = atomicAdd(&g_base, sm[t]);  // claim block range
    __syncthreads();
    if (idx < Nn) {
        int excl = sbase + sm[t] - vp;                   // block-local exclusive + base
        g_off[idx] = excl;
        g_cur[idx] = excl;
        if (v & 1) g_csr[excl + v] = make_int2(0, 0);    // pad record: weight 0
    }
}

// fill writes EVERY claimed slot (invalid src -> {0, nrm=0}), so gather needs no guard
__global__ void k_fill(const int* __restrict__ ei) {
    int e = blockIdx.x * blockDim.x + threadIdx.x;
    if (e >= Ee) return;
    unsigned s = (unsigned)ei[e];
    unsigned d = (unsigned)ei[Ee + e];
    if (d >= Nn) return;
    int   ssrc = 0;
    float nrm  = 0.0f;
    if (s < Nn) { ssrc = (int)s; nrm = g_dinv[s] * g_dinv[d]; }
    int slot = atomicAdd(&g_cur[d], 1);
    g_csr[slot] = make_int2(ssrc, __float_as_int(nrm));
}

// ---------------- layer 1 linear: g_h = half(x @ W1) (R10 core, fp16 epilogue) ----
__global__ void k_lin1(const float* __restrict__ x, const float* __restrict__ W1) {
    __shared__ __align__(16) float Ws[256 * 16];
    int tid = threadIdx.x;
#pragma unroll 4
    for (int i = tid; i < 256 * 16; i += 256) {
        int k = i >> 4, o = i & 15;
        int slot = (o >> 2) ^ ((k >> 1) & 3);
        Ws[(k << 4) + (slot << 2) + (o & 3)] = W1[i];
    }
    __syncthreads();

    int warp = tid >> 5, lane = tid & 31;
    int r0 = (blockIdx.x * 8 + warp) * 4;

    unsigned long long acc2[32];
#pragma unroll
    for (int j = 0; j < 32; j++) acc2[j] = 0ULL;

#pragma unroll
    for (int s = 0; s < 8; s++) {
        int k = (s << 5) | lane;
        float x0 = x[(size_t)(r0 + 0) * 256 + k];
        float x1 = x[(size_t)(r0 + 1) * 256 + k];
        float x2 = x[(size_t)(r0 + 2) * 256 + k];
        float x3 = x[(size_t)(r0 + 3) * 256 + k];
        unsigned long long xp0 = pack2(x0, x0);
        unsigned long long xp1 = pack2(x1, x1);
        unsigned long long xp2 = pack2(x2, x2);
        unsigned long long xp3 = pack2(x3, x3);

        const ulonglong2* wrow = (const ulonglong2*)(Ws + (k << 4));
        int sw = (k >> 1) & 3;
        ulonglong2 wq0 = wrow[0 ^ sw];
        ulonglong2 wq1 = wrow[1 ^ sw];
        ulonglong2 wq2 = wrow[2 ^ sw];
        ulonglong2 wq3 = wrow[3 ^ sw];
        unsigned long long w2[8] = {wq0.x, wq0.y, wq1.x, wq1.y, wq2.x, wq2.y, wq3.x, wq3.y};

#pragma unroll
        for (int o2 = 0; o2 < 8; o2++) {
            acc2[0 * 8 + o2] = fma2(xp0, w2[o2], acc2[0 * 8 + o2]);
            acc2[1 * 8 + o2] = fma2(xp1, w2[o2], acc2[1 * 8 + o2]);
            acc2[2 * 8 + o2] = fma2(xp2, w2[o2], acc2[2 * 8 + o2]);
            acc2[3 * 8 + o2] = fma2(xp3, w2[o2], acc2[3 * 8 + o2]);
        }
    }

    float vals[64];
#pragma unroll
    for (int j = 0; j < 32; j++) unpack2(vals[2 * j], vals[2 * j + 1], acc2[j]);

    const unsigned FULL = 0xffffffffu;
#define FOLD_STAGE(n, m)                                                        \
    {                                                                           \
        bool hi = (lane & (m)) != 0;                                            \
        _Pragma("unroll")                                                       \
        for (int t = 0; t < (n) / 2; t++) {                                     \
            float mine = hi ? vals[t + (n) / 2] : vals[t];                      \
            float send = hi ? vals[t] : vals[t + (n) / 2];                      \
            vals[t] = mine + __shfl_xor_sync(FULL, send, (m));                  \
        }                                                                       \
    }
    FOLD_STAGE(64, 16)
    FOLD_STAGE(32, 8)
    FOLD_STAGE(16, 4)
    FOLD_STAGE(8, 2)
    FOLD_STAGE(4, 1)
#undef FOLD_STAGE

    int i = (((lane >> 4) & 1) << 1) | ((lane >> 3) & 1);
    int o = (((lane >> 2) & 1) << 3) | (((lane >> 1) & 1) << 2) | ((lane & 1) << 1);
    int row = r0 + i;
    __half2 hp = __floats2half2_rn(vals[0], vals[1]);     // cols o, o+1
    ((unsigned*)g_h)[row * 8 + (o >> 1)] = *(unsigned*)&hp;
}

// ---------------- gather core (quad-per-node, padded CSR, branch-free) ----------
__device__ __forceinline__ float4 gather_node(int node, int t) {
    int beg  = g_off[node];                 // always even
    int cnt  = g_deg[node];
    int nit  = (cnt + 1) >> 1;              // int4 iterations over padded records
    float di = g_dinv[node];
    float ss = di * di;

    const uint2* h2 = (const uint2*)g_h;    // 8B granule: index = node*4 + t
    uint2 araw = h2[(node << 2) + t];
    float2 a01 = __half22float2(*(__half2*)&araw.x);
    float2 a23 = __half22float2(*(__half2*)&araw.y);
    float4 acc;
    acc.x = ss * a01.x; acc.y = ss * a01.y; acc.z = ss * a23.x; acc.w = ss * a23.y;

    const int4* cp = (const int4*)(g_csr + beg);
#pragma unroll 4
    for (int it = 0; it < nit; it++) {
        int4 rr = cp[it];                   // 2 records: {s0, n0, s1, n1}
        float w0 = __int_as_float(rr.y);
        float w1 = __int_as_float(rr.w);
        uint2 vr0 = h2[((unsigned)rr.x << 2) + t];
        uint2 vr1 = h2[((unsigned)rr.z << 2) + t];
        float2 p01 = __half22float2(*(__half2*)&vr0.x);
        float2 p23 = __half22float2(*(__half2*)&vr0.y);
        float2 q01 = __half22float2(*(__half2*)&vr1.x);
        float2 q23 = __half22float2(*(__half2*)&vr1.y);
        acc.x = fmaf(w0, p01.x, acc.x);
        acc.y = fmaf(w0, p01.y, acc.y);
        acc.z = fmaf(w0, p23.x, acc.z);
        acc.w = fmaf(w0, p23.y, acc.w);
        acc.x = fmaf(w1, q01.x, acc.x);
        acc.y = fmaf(w1, q01.y, acc.y);
        acc.z = fmaf(w1, q23.x, acc.z);
        acc.w = fmaf(w1, q23.y, acc.w);
    }
    return acc;
}

// gather + bias + fused BN stats (sum/sumsq per column into g_stats[so..])
__global__ void k_gather_agg(const float* __restrict__ bias, int so) {
    __shared__ float bsum[16], bsq[16];
    if (threadIdx.x < 16) { bsum[threadIdx.x] = 0.0f; bsq[threadIdx.x] = 0.0f; }
    __syncthreads();

    int gid  = blockIdx.x * blockDim.x + threadIdx.x;
    int node = gid >> 2;
    int t    = gid & 3;
    int lane = threadIdx.x & 31;

    float4 acc = gather_node(node, t);
    float4 b4  = ((const float4*)bias)[t];
    acc.x += b4.x; acc.y += b4.y; acc.z += b4.z; acc.w += b4.w;
    ((float4*)g_agg)[(node << 2) + t] = acc;

    float4 s1 = acc;
    float4 s2;
    s2.x = acc.x * acc.x; s2.y = acc.y * acc.y; s2.z = acc.z * acc.z; s2.w = acc.w * acc.w;
    const unsigned FULL = 0xffffffffu;
#pragma unroll
    for (int m = 4; m <= 16; m <<= 1) {
        s1.x += __shfl_xor_sync(FULL, s1.x, m);
        s1.y += __shfl_xor_sync(FULL, s1.y, m);
        s1.z += __shfl_xor_sync(FULL, s1.z, m);
        s1.w += __shfl_xor_sync(FULL, s1.w, m);
        s2.x += __shfl_xor_sync(FULL, s2.x, m);
        s2.y += __shfl_xor_sync(FULL, s2.y, m);
        s2.z += __shfl_xor_sync(FULL, s2.z, m);
        s2.w += __shfl_xor_sync(FULL, s2.w, m);
    }
    if (lane < 4) {
        atomicAdd(&bsum[t * 4 + 0], s1.x);
        atomicAdd(&bsum[t * 4 + 1], s1.y);
        atomicAdd(&bsum[t * 4 + 2], s1.z);
        atomicAdd(&bsum[t * 4 + 3], s1.w);
        atomicAdd(&bsq[t * 4 + 0], s2.x);
        atomicAdd(&bsq[t * 4 + 1], s2.y);
        atomicAdd(&bsq[t * 4 + 2], s2.z);
        atomicAdd(&bsq[t * 4 + 3], s2.w);
    }
    __syncthreads();
    if (threadIdx.x < 16) {
        atomicAdd(&g_stats[so + threadIdx.x], bsum[threadIdx.x]);
        atomicAdd(&g_stats[so + 16 + threadIdx.x], bsq[threadIdx.x]);
    }
}

__global__ void k_gather_out(float* __restrict__ out, const float* __restrict__ bias) {
    int gid  = blockIdx.x * blockDim.x + threadIdx.x;
    int node = gid >> 2;
    if (node >= Nn) return;
    int t = gid & 3;
    float4 acc = gather_node(node, t);
    float4 b4  = ((const float4*)bias)[t];
    acc.x += b4.x; acc.y += b4.y; acc.z += b4.z; acc.w += b4.w;
    ((float4*)out)[(node << 2) + t] = acc;
}

// ---------------- fused BNfinal+BN+ReLU+16x16 linear (fp16 h output) ----------------
__global__ void k_lin_mid(const float* __restrict__ W,
                          const float* __restrict__ gamma,
                          const float* __restrict__ beta, int so) {
    __shared__ float Ws[256];
    __shared__ float sc_s[16], sh_s[16];
    if (threadIdx.x < 256) Ws[threadIdx.x] = W[threadIdx.x];
    if (threadIdx.x < 16) {
        float sum = g_stats[so + threadIdx.x];
        float sq  = g_stats[so + 16 + threadIdx.x];
        float mu  = sum / (float)Nn;
        float var = sq / (float)Nn - mu * mu;
        float sc  = gamma[threadIdx.x] * rsqrtf(var + EPSV);
        sc_s[threadIdx.x] = sc;
        sh_s[threadIdx.x] = beta[threadIdx.x] - mu * sc;
    }
    __syncthreads();

    int row = blockIdx.x * blockDim.x + threadIdx.x;
    if (row >= Nn) return;

    float z[16];
    const float4* ap = (const float4*)(g_agg + (size_t)row * 16);
#pragma unroll
    for (int j = 0; j < 4; j++) {
        float4 v = ap[j];
        const float* vv = (const float*)&v;
#pragma unroll
        for (int i = 0; i < 4; i++) {
            int k = j * 4 + i;
            z[k] = fmaxf(fmaf(sc_s[k], vv[i], sh_s[k]), 0.0f);
        }
    }

    float o[16];
#pragma unroll
    for (int c = 0; c < 16; c++) o[c] = 0.0f;
#pragma unroll
    for (int k = 0; k < 16; k++) {
        float zk = z[k];
        const float* wr = &Ws[k * 16];
#pragma unroll
        for (int c = 0; c < 16; c++) o[c] = fmaf(zk, wr[c], o[c]);
    }

    // emit fp16: 16 cols -> 8 half2 -> 2x uint4
    uint4* hv = (uint4*)((__half*)g_h + (size_t)row * 16);
#pragma unroll
    for (int j = 0; j < 2; j++) {
        __half2 h0 = __floats2half2_rn(o[j*8+0], o[j*8+1]);
        __half2 h1 = __floats2half2_rn(o[j*8+2], o[j*8+3]);
        __half2 h2 = __floats2half2_rn(o[j*8+4], o[j*8+5]);
        __half2 h3 = __floats2half2_rn(o[j*8+6], o[j*8+7]);
        uint4 st;
        st.x = *(unsigned*)&h0;
        st.y = *(unsigned*)&h1;
        st.z = *(unsigned*)&h2;
        st.w = *(unsigned*)&h3;
        hv[j] = st;
    }
}

// ---------------- launch ----------------
extern "C" void kernel_launch(void* const* d_in, const int* in_sizes, int n_in,
                              void* d_out, int out_size) {
    // Identify inputs by SIZE (robust to metadata ordering)
    const float* x  = nullptr;
    const int*   ei = nullptr;
    const float* W1 = nullptr;
    const float* W2 = nullptr;
    const float* W3 = nullptr;
    const float* v16[8] = {nullptr};
    int n16 = 0;
    for (int i = 0; i < n_in; i++) {
        int sz = in_sizes[i];
        if      (sz == 51200000) x  = (const float*)d_in[i];
        else if (sz == 6400000)  ei = (const int*)d_in[i];
        else if (sz == 4096)     W1 = (const float*)d_in[i];
        else if (sz == 256)      { if (!W2) W2 = (const float*)d_in[i]; else W3 = (const float*)d_in[i]; }
        else if (sz == 16 && n16 < 8) v16[n16++] = (const float*)d_in[i];
    }
    const float* b1  = v16[0];
    const float* g1  = v16[1];
    const float* be1 = v16[2];
    const float* b2  = v16[3];
    const float* g2  = v16[4];
    const float* be2 = v16[5];
    const float* b3  = v16[6];
    float* out = (float*)d_out;

    const int TB    = 256;
    const int nblk  = (Nn + TB - 1) / TB;
    const int eblk  = (Ee + TB - 1) / TB;
    const int l1blk = Nn / 32;              // 6250 (8 warps x 4 rows, exact)
    const int gblk  = (Nn * 4) / TB;        // 3125 exact

    // ----- CSR build + lin1 (lin1 at launch index 3 => profiled control slot) -----
    k_init<<<nblk, TB>>>();                 // 0
    k_deg_count<<<eblk, TB>>>(ei);          // 1
    k_scanA<<<SBLK, SB>>>();                // 2: single-pass scan (unordered partition)
    k_lin1<<<l1blk, TB>>>(x, W1);           // 3  <-- profiled
    k_fill<<<eblk, TB>>>(ei);               // 4

    // ----- layer 1 -----
    k_gather_agg<<<gblk, TB>>>(b1, 0);      // 5
    // ----- layer 2 -----
    k_lin_mid<<<nblk, TB>>>(W2, g1, be1, 0);    // 6
    k_gather_agg<<<gblk, TB>>>(b2, 32);         // 7
    // ----- layer 3 -----
    k_lin_mid<<<nblk, TB>>>(W3, g2, be2, 32);   // 8
    k_gather_out<<<gblk, TB>>>(out, b3);        // 9
}